// round 13
// baseline (speedup 1.0000x reference)
#include <cuda_runtime.h>

// ---------------------------------------------------------------------------
// SSIM (5x5 Gaussian, sigma=1.5, SAME zero padding), fused single kernel.
// R13 = R11 (per-warp syncwarp staging, masked weights, row peeling,
//       (s,d) transform, register ring, 1-row prefetch) with the load fix
//       R12 aimed for, but WITHOUT the block barrier:
//   - main loads: own column x0+lane -> 128B-aligned, always in-bounds
//     (no clamp, no SEL), 1 cache line instead of 2.
//   - halo loads: predicated to lanes 0..3 (4 cols x 3 ch, clamped);
//     predicated-off lanes generate no L1 wavefronts. ~2x fewer LDG
//     wavefronts per step overall.
// ---------------------------------------------------------------------------

constexpr int W    = 512;
constexpr int H    = 512;
constexpr int C    = 3;
constexpr int NB   = 16;
constexpr int BX   = 128;   // output columns per block (4 warps x 32)
constexpr int ROWS = 32;    // output rows per block

typedef unsigned long long u64;

__device__ __forceinline__ u64 pk2(float lo, float hi) {
    u64 r;
    asm("mov.b64 %0, {%1, %2};" : "=l"(r) : "f"(lo), "f"(hi));
    return r;
}
__device__ __forceinline__ void up2(u64 v, float& lo, float& hi) {
    asm("mov.b64 {%0, %1}, %2;" : "=f"(lo), "=f"(hi) : "l"(v));
}
__device__ __forceinline__ u64 fma2_(u64 a, u64 b, u64 c) {
    u64 d;
    asm("fma.rn.f32x2 %0, %1, %2, %3;" : "=l"(d) : "l"(a), "l"(b), "l"(c));
    return d;
}
__device__ __forceinline__ u64 mul2_(u64 a, u64 b) {
    u64 d;
    asm("mul.rn.f32x2 %0, %1, %2;" : "=l"(d) : "l"(a), "l"(b));
    return d;
}

__global__ __launch_bounds__(128, 4)
void ssim_kernel(const float* __restrict__ img1,
                 const float* __restrict__ img2,
                 const float* __restrict__ win,
                 float* __restrict__ out)
{
    // Per-warp row buffer. Entry e holds col x0-2+e (e = 0..35):
    // e=0,1 left halo, e=2..33 own cols (lane -> 2+lane), e=34,35 right halo.
    __shared__ float2 sSD[4][C][36];

    const int lane = threadIdx.x & 31;
    const int warp = threadIdx.x >> 5;
    const int b    = blockIdx.z;
    const int y0   = blockIdx.y * ROWS;
    const int x0   = blockIdx.x * BX + warp * 32;
    const int xo   = x0 + lane;           // own column (always in [0,W))

    // Halo duty: lanes 0..3, one halo column each (all channels).
    const bool duty   = (lane < 4);
    const int  hcol   = (lane < 2) ? (x0 - 2 + lane) : (x0 + 30 + lane);
    const int  hentry = (lane < 2) ? lane : (32 + lane);
    const int  hcolc  = hcol < 0 ? 0 : (hcol > W - 1 ? W - 1 : hcol);

    // Separable 1D Gaussian: g[j] = w2d[2][j] / sqrt(w2d[2][2]).
    const float gc = sqrtf(win[12]);
    u64 wg[5];    // vertical weights (unmasked)
    u64 wgm[5];   // horizontal weights, masked by this lane's tap validity
#pragma unroll
    for (int j = 0; j < 5; ++j) {
        const float gj = __fdividef(win[10 + j], gc);
        wg[j] = pk2(gj, gj);
        const int tapcol = xo - 2 + j;
        const float mj = (tapcol >= 0 && tapcol < W) ? gj : 0.0f;
        wgm[j] = pk2(mj, mj);
    }

    int cb[C];
#pragma unroll
    for (int c = 0; c < C; ++c) cb[c] = ((b * C + c) * H) * W;

    // Rolling horizontal-filtered state: 5 row slots per channel (packed).
    u64 hSD[C][5], hSQ[C][5];

    // One-row-ahead prefetch registers.
    float pa[C], pb[C];    // own column (aligned, in-bounds)
    float qa[C], qb[C];    // halo column (duty lanes only)

    auto loadrow_u = [&](int r) {       // interior rows: no checks at all
        const int rr = r * W;
#pragma unroll
        for (int c = 0; c < C; ++c) {
            const int o = cb[c] + rr + xo;
            pa[c] = img1[o];
            pb[c] = img2[o];
        }
        if (duty) {
#pragma unroll
            for (int c = 0; c < C; ++c) {
                const int o = cb[c] + rr + hcolc;
                qa[c] = img1[o];
                qb[c] = img2[o];
            }
        }
    };
    auto loadrow_c = [&](int r) {       // top/bottom rows: zero if OOB
        const bool rok = (r >= 0) && (r < H);
        const int rr = (rok ? r : 0) * W;
        float ta[C], tb[C], ua[C], ub[C];
#pragma unroll
        for (int c = 0; c < C; ++c) {
            const int o = cb[c] + rr + xo;
            ta[c] = img1[o];
            tb[c] = img2[o];
        }
        if (duty) {
#pragma unroll
            for (int c = 0; c < C; ++c) {
                const int o = cb[c] + rr + hcolc;
                ua[c] = img1[o];
                ub[c] = img2[o];
            }
        }
#pragma unroll
        for (int c = 0; c < C; ++c) {
            pa[c] = rok ? ta[c] : 0.0f;
            pb[c] = rok ? tb[c] : 0.0f;
            qa[c] = (rok && duty) ? ua[c] : 0.0f;
            qb[c] = (rok && duty) ? ub[c] : 0.0f;
        }
    };

    const float C1 = 0.0001f;  // (0.01)^2
    const float C2 = 0.0009f;  // (0.03)^2

    // One pipeline step. S5 = s % 5 compile-time so the ring stays in
    // registers. prefetch loads the row for step s+1.
    auto step = [&](int s, int S5, auto&& prefetch) {
        // ---- store prefetched row s to smem as (s,d) ----
        __syncwarp();
#pragma unroll
        for (int c = 0; c < C; ++c) {
            sSD[warp][c][2 + lane] = make_float2(pa[c] + pb[c], pa[c] - pb[c]);
            if (duty)
                sSD[warp][c][hentry] =
                    make_float2(qa[c] + qb[c], qa[c] - qb[c]);
        }
        __syncwarp();

        // ---- prefetch next row (hidden behind compute below) ----
        prefetch();

        // ---- horizontal 5-tap pass into slot S5 (masked weights).
        //      Tap j of column xo lives at entry lane + j (unit stride). ----
#pragma unroll
        for (int c = 0; c < C; ++c) {
            const u64* p = (const u64*)&sSD[warp][c][0];
            u64 ssd = 0ull, ssq = 0ull;
#pragma unroll
            for (int j = 0; j < 5; ++j) {
                const u64 pp = p[lane + j];
                ssd = fma2_(pp, wgm[j], ssd);
                ssq = fma2_(mul2_(pp, pp), wgm[j], ssq);
            }
            hSD[c][S5] = ssd;
            hSQ[c][S5] = ssq;
        }

        // ---- vertical 5-tap + epilogue for output row y0+s-4 ----
        if (s >= 4) {
            float num[C], den[C];
#pragma unroll
            for (int c = 0; c < C; ++c) {
                u64 vsd = 0ull, vsq = 0ull;
#pragma unroll
                for (int j = 0; j < 5; ++j) {
                    const int slot = (S5 + 1 + j) % 5;  // row s-4+j
                    vsd = fma2_(hSD[c][slot], wg[j], vsd);
                    vsq = fma2_(hSQ[c][slot], wg[j], vsq);
                }
                float cs, cd, css, csd;
                up2(vsd, cs, cd);     // conv(s), conv(d)
                up2(vsq, css, csd);   // conv(s^2), conv(d^2)
                const float cs2 = cs * cs, cd2 = cd * cd;
                const float m12 = (cs2 - cd2) * 0.25f;   // mu1*mu2
                const float msq = (cs2 + cd2) * 0.5f;    // mu1^2+mu2^2
                const float cab = (css - csd) * 0.25f;   // conv(ab)
                const float csum = (css + csd) * 0.5f;   // conv(a2)+conv(b2)
                const float s12  = cab - m12;            // sigma12
                const float svar = csum - msq;           // var1+var2
                num[c] = (2.0f * m12 + C1) * (2.0f * s12 + C2);
                den[c] = (msq + C1) * (svar + C2);
            }
            const float d01   = den[0] * den[1];
            const float denom = d01 * den[2];
            float numer = num[2] * d01;
            numer = fmaf(num[0], den[1] * den[2], numer);
            numer = fmaf(num[1], den[0] * den[2], numer);
            const int y = y0 + s - 4;
            out[(b * H + y) * W + xo] =
                __fdividef(numer, denom) * (1.0f / 3.0f);
        }
    };

    // ---- pipeline ----
    loadrow_c(y0 - 2);                               // row for step 0
    step(0, 0, [&] { loadrow_c(y0 - 1); });          // top, may be OOB
    step(1, 1, [&] { loadrow_u(y0); });              // row y0 valid

    for (int base = 2; base < 32; base += 5) {       // steady: s = 2..31
#pragma unroll
        for (int k = 0; k < 5; ++k) {
            // rows y0+1 .. y0+30: always valid -> unchecked loads
            step(base + k, (k + 2) % 5,
                 [&] { loadrow_u(y0 - 1 + base + k); });
        }
    }

    step(32, 2, [&] { loadrow_u(y0 + 31); });        // row y0+31 valid
    step(33, 3, [&] { loadrow_c(y0 + 32); });        // bottom, may be OOB
    step(34, 4, [&] { loadrow_c(y0 + 33); });        // bottom, may be OOB
    step(35, 0, [&] {});                             // last step
}

extern "C" void kernel_launch(void* const* d_in, const int* in_sizes, int n_in,
                              void* d_out, int out_size)
{
    const float* img1 = (const float*)d_in[0];
    const float* img2 = (const float*)d_in[1];
    const float* win  = (const float*)d_in[2];
    float* out = (float*)d_out;

    dim3 grid(W / BX, H / ROWS, NB);  // (4, 16, 16) = 1024 blocks
    ssim_kernel<<<grid, 128>>>(img1, img2, win, out);
}

// round 14
// speedup vs baseline: 1.0386x; 1.0386x over previous
#include <cuda_runtime.h>

// ---------------------------------------------------------------------------
// SSIM (5x5 Gaussian, sigma=1.5, SAME zero padding), fused single kernel.
// R14 = R11 (loads/weights/ring identical) + per-warp DOUBLE-BUFFERED smem:
//   - parity P = s&1: STS row s -> buf[P]; ONE __syncwarp; LDS from buf[P].
//     The old second sync is redundant: remaining hazards are same-warp
//     program-order (per-warp smem ops retire in order).
//   - steps 0..3 peeled -> steady loop has no epilogue branch.
// ---------------------------------------------------------------------------

constexpr int W    = 512;
constexpr int H    = 512;
constexpr int C    = 3;
constexpr int NB   = 16;
constexpr int BX   = 128;   // output columns per block (4 warps x 32)
constexpr int ROWS = 32;    // output rows per block

typedef unsigned long long u64;

__device__ __forceinline__ u64 pk2(float lo, float hi) {
    u64 r;
    asm("mov.b64 %0, {%1, %2};" : "=l"(r) : "f"(lo), "f"(hi));
    return r;
}
__device__ __forceinline__ void up2(u64 v, float& lo, float& hi) {
    asm("mov.b64 {%0, %1}, %2;" : "=f"(lo), "=f"(hi) : "l"(v));
}
__device__ __forceinline__ u64 fma2_(u64 a, u64 b, u64 c) {
    u64 d;
    asm("fma.rn.f32x2 %0, %1, %2, %3;" : "=l"(d) : "l"(a), "l"(b), "l"(c));
    return d;
}
__device__ __forceinline__ u64 mul2_(u64 a, u64 b) {
    u64 d;
    asm("mul.rn.f32x2 %0, %1, %2;" : "=l"(d) : "l"(a), "l"(b));
    return d;
}

__global__ __launch_bounds__(128, 4)
void ssim_kernel(const float* __restrict__ img1,
                 const float* __restrict__ img2,
                 const float* __restrict__ win,
                 float* __restrict__ out)
{
    // Per-warp double row buffer. Entry e of a buffer holds col x0-2+e.
    __shared__ float2 sSD[4][2][C][36];

    const int lane = threadIdx.x & 31;
    const int warp = threadIdx.x >> 5;
    const int b    = blockIdx.z;
    const int y0   = blockIdx.y * ROWS;
    const int x0   = blockIdx.x * BX + warp * 32;
    const int xo   = x0 + lane;           // output col (always < W)
    const int gx   = x0 - 2 + lane;       // main load col (may be < 0)
    const int gx2  = x0 + 30 + lane;      // halo load col (may be >= W)

    // Clamped load columns (garbage masked by consumer weights).
    const int gxc  = gx < 0 ? 0 : gx;
    const int gx2c = gx2 > (W - 1) ? (W - 1) : gx2;

    // Separable 1D Gaussian: g[j] = w2d[2][j] / sqrt(w2d[2][2]).
    const float gc = sqrtf(win[12]);
    u64 wg[5];    // vertical weights (unmasked)
    u64 wgm[5];   // horizontal weights, masked by this lane's tap validity
#pragma unroll
    for (int j = 0; j < 5; ++j) {
        const float gj = __fdividef(win[10 + j], gc);
        wg[j] = pk2(gj, gj);
        const int tapcol = xo - 2 + j;
        const float mj = (tapcol >= 0 && tapcol < W) ? gj : 0.0f;
        wgm[j] = pk2(mj, mj);
    }

    int cb[C];
#pragma unroll
    for (int c = 0; c < C; ++c) cb[c] = ((b * C + c) * H) * W;

    // Rolling horizontal-filtered state: 5 row slots per channel (packed).
    u64 hSD[C][5], hSQ[C][5];

    // One-row-ahead prefetch registers (raw a, b; main + halo), R11-exact.
    float pa[C], pb[C], qa[C], qb[C];

    auto loadrow_u = [&](int r) {       // interior rows: no checks at all
        const int rr = r * W;
#pragma unroll
        for (int c = 0; c < C; ++c) {
            const int o = cb[c] + rr;
            pa[c] = img1[o + gxc];
            pb[c] = img2[o + gxc];
            qa[c] = img1[o + gx2c];
            qb[c] = img2[o + gx2c];
        }
    };
    auto loadrow_c = [&](int r) {       // top/bottom rows: zero if OOB
        const bool rok = (r >= 0) && (r < H);
        const int rr = (rok ? r : 0) * W;
        float ta[C], tb[C], ua[C], ub[C];
#pragma unroll
        for (int c = 0; c < C; ++c) {
            const int o = cb[c] + rr;
            ta[c] = img1[o + gxc];
            tb[c] = img2[o + gxc];
            ua[c] = img1[o + gx2c];
            ub[c] = img2[o + gx2c];
        }
#pragma unroll
        for (int c = 0; c < C; ++c) {
            pa[c] = rok ? ta[c] : 0.0f;
            pb[c] = rok ? tb[c] : 0.0f;
            qa[c] = rok ? ua[c] : 0.0f;
            qb[c] = rok ? ub[c] : 0.0f;
        }
    };

    const float C1 = 0.0001f;  // (0.01)^2
    const float C2 = 0.0009f;  // (0.03)^2

    // One pipeline step. S5 = s % 5, P = s & 1, EPI: compile-time.
    auto step = [&](int s, int S5, int P, bool EPI, auto&& prefetch) {
        // ---- store row s (prefetch regs) into buf[P] as (s,d) ----
#pragma unroll
        for (int c = 0; c < C; ++c) {
            sSD[warp][P][c][lane] = make_float2(pa[c] + pb[c], pa[c] - pb[c]);
            if (lane < 4)
                sSD[warp][P][c][32 + lane] =
                    make_float2(qa[c] + qb[c], qa[c] - qb[c]);
        }
        __syncwarp();   // single sync: neighbors' STS visible before LDS

        // ---- prefetch next row (hidden behind compute below) ----
        prefetch();

        // ---- horizontal 5-tap pass into slot S5 (masked weights) ----
#pragma unroll
        for (int c = 0; c < C; ++c) {
            const u64* p = (const u64*)&sSD[warp][P][c][0];
            u64 ssd = 0ull, ssq = 0ull;
#pragma unroll
            for (int j = 0; j < 5; ++j) {
                const u64 pp = p[lane + j];
                ssd = fma2_(pp, wgm[j], ssd);
                ssq = fma2_(mul2_(pp, pp), wgm[j], ssq);
            }
            hSD[c][S5] = ssd;
            hSQ[c][S5] = ssq;
        }

        // ---- vertical 5-tap + epilogue for output row y0+s-4 ----
        if (EPI) {
            float num[C], den[C];
#pragma unroll
            for (int c = 0; c < C; ++c) {
                u64 vsd = 0ull, vsq = 0ull;
#pragma unroll
                for (int j = 0; j < 5; ++j) {
                    const int slot = (S5 + 1 + j) % 5;  // row s-4+j
                    vsd = fma2_(hSD[c][slot], wg[j], vsd);
                    vsq = fma2_(hSQ[c][slot], wg[j], vsq);
                }
                float cs, cd, css, csd;
                up2(vsd, cs, cd);     // conv(s), conv(d)
                up2(vsq, css, csd);   // conv(s^2), conv(d^2)
                const float cs2 = cs * cs, cd2 = cd * cd;
                const float m12 = (cs2 - cd2) * 0.25f;   // mu1*mu2
                const float msq = (cs2 + cd2) * 0.5f;    // mu1^2+mu2^2
                const float cab = (css - csd) * 0.25f;   // conv(ab)
                const float csum = (css + csd) * 0.5f;   // conv(a2)+conv(b2)
                const float s12  = cab - m12;            // sigma12
                const float svar = csum - msq;           // var1+var2
                num[c] = (2.0f * m12 + C1) * (2.0f * s12 + C2);
                den[c] = (msq + C1) * (svar + C2);
            }
            const float d01   = den[0] * den[1];
            const float denom = d01 * den[2];
            float numer = num[2] * d01;
            numer = fmaf(num[0], den[1] * den[2], numer);
            numer = fmaf(num[1], den[0] * den[2], numer);
            const int y = y0 + s - 4;
            out[(b * H + y) * W + xo] =
                __fdividef(numer, denom) * (1.0f / 3.0f);
        }
    };

    // ---- pipeline (S5 = s%5, P = s&1 all compile-time) ----
    loadrow_c(y0 - 2);                                   // row for step 0
    step(0, 0, 0, false, [&] { loadrow_c(y0 - 1); });    // top, may be OOB
    step(1, 1, 1, false, [&] { loadrow_u(y0); });
    step(2, 2, 0, false, [&] { loadrow_u(y0 + 1); });
    step(3, 3, 1, false, [&] { loadrow_u(y0 + 2); });

    // Steady: s = 4..23 (rows prefetched are y0+3 .. y0+22, always valid).
    // base % 10 == 4 so (base+k)%5 == (k+4)%5 and (base+k)&1 == k&1.
    for (int base = 4; base < 24; base += 10) {
#pragma unroll
        for (int k = 0; k < 10; ++k) {
            step(base + k, (k + 4) % 5, k & 1, true,
                 [&] { loadrow_u(y0 - 1 + base + k); });
        }
    }

    // s = 24..33: prefetch rows y0+23 .. y0+31 unchecked, y0+32 checked.
    {
        const int base = 24;
#pragma unroll
        for (int k = 0; k < 10; ++k) {
            step(base + k, (k + 4) % 5, k & 1, true, [&] {
                if (k < 9) loadrow_u(y0 - 1 + base + k);
                else       loadrow_c(y0 + 32);
            });
        }
    }

    step(34, 4, 0, true, [&] { loadrow_c(y0 + 33); });   // bottom, may be OOB
    step(35, 0, 1, true, [&] {});                        // last step
}

extern "C" void kernel_launch(void* const* d_in, const int* in_sizes, int n_in,
                              void* d_out, int out_size)
{
    const float* img1 = (const float*)d_in[0];
    const float* img2 = (const float*)d_in[1];
    const float* win  = (const float*)d_in[2];
    float* out = (float*)d_out;

    dim3 grid(W / BX, H / ROWS, NB);  // (4, 16, 16) = 1024 blocks
    ssim_kernel<<<grid, 128>>>(img1, img2, win, out);
}